// round 11
// baseline (speedup 1.0000x reference)
#include <cuda_runtime.h>
#include <math.h>

typedef unsigned long long ull;

#define CB 32
#define CT 40
#define CP 12
#define CE 2048
#define CH 1024
#define CM (CB*CT*CP)     /* 15360 rows of (b,t,p) */
#define CBP (CB*CP)       /* 384 GRU state rows */

/* ---------------- scratch (device globals; no allocation allowed) -------- */
__device__ float g_x  [CM * CH];
__device__ float g_gx [CM * 3 * CH];
__device__ float g_hid[CM * CH];
__device__ float g_h0 [CBP * CH];
__device__ float g_h1 [CBP * CH];

/* ---------------- packed fp32x2 FMA (Blackwell FFMA2) -------------------- */
__device__ __forceinline__ void ffma2(ull& d, ull a, ull b) {
    asm("fma.rn.f32x2 %0, %1, %2, %0;" : "+l"(d) : "l"(a), "l"(b));
}
__device__ __forceinline__ float2 upk(ull v) {
    return *reinterpret_cast<float2*>(&v);
}

/* ================= big GEMM: C[m,n] = act(A[m,:]·W[n,:] + b[n]) ==========
 * Tile 96m x 128n, BK=16, 384 threads (acc 16 f32x2 = 32 regs -> 2 blocks
 * co-resident per SM). A natural smem (broadcast LDS.128), W dup (w,w).
 * Inner loop per kk: 1 a-LDS.128 + 4 b-LDS.128 + 16 FFMA2.
 * Loaders read 64B contiguous per 4 threads (8 lines/warp-LDG).           */
#define BM 96
#define BN 128
#define BKg 16
#define ASTR 100      /* As row stride (floats) */
#define BSTR 260      /* Bs row stride (floats): 4-way store conflict max */

__global__ __launch_bounds__(384) void gemm_f32x2(
    const float* __restrict__ A, const float* __restrict__ W,
    const float* __restrict__ bias, float* __restrict__ C,
    int N, int K, int act)
{
    __shared__ __align__(16) float As[BKg][ASTR];
    __shared__ __align__(16) float Bs[BKg][BSTR];

    const int tid = threadIdx.x;
    const int tx  = tid & 15;          /* col pair per 32-group      */
    const int ty  = tid >> 4;          /* 0..23: rows 4ty..4ty+3     */
    const int lr  = tid >> 2;          /* loader row 0..95           */
    const int lk  = (tid & 3) << 2;    /* loader k: 0,4,8,12         */

    const float* Ag  = A + (size_t)(blockIdx.y * BM + lr) * K + lk;
    const float* Wg0 = W + (size_t)(blockIdx.x * BN + lr) * K + lk;
    const float* Wg1 = W + (size_t)(blockIdx.x * BN + 96 + (lr & 31)) * K + lk;
    const bool   wb1 = (lr < 32);      /* tid<128 handles B rows 96..127 */

    ull acc[2][8];
#pragma unroll
    for (int i = 0; i < 2; i++)
#pragma unroll
        for (int j = 0; j < 8; j++) acc[i][j] = 0ULL;

    float4 pa  = *(const float4*)Ag;
    float4 pb0 = *(const float4*)Wg0;
    float4 pb1 = wb1 ? *(const float4*)Wg1 : make_float4(0.f,0.f,0.f,0.f);

    const int nch = K / BKg;
    for (int c = 0; c < nch; ++c) {
        __syncthreads();
        As[lk+0][lr] = pa.x;  As[lk+1][lr] = pa.y;
        As[lk+2][lr] = pa.z;  As[lk+3][lr] = pa.w;
        *(float2*)&Bs[lk+0][2*lr] = make_float2(pb0.x, pb0.x);
        *(float2*)&Bs[lk+1][2*lr] = make_float2(pb0.y, pb0.y);
        *(float2*)&Bs[lk+2][2*lr] = make_float2(pb0.z, pb0.z);
        *(float2*)&Bs[lk+3][2*lr] = make_float2(pb0.w, pb0.w);
        if (wb1) {
            int r2 = 2*(96 + (lr & 31));
            *(float2*)&Bs[lk+0][r2] = make_float2(pb1.x, pb1.x);
            *(float2*)&Bs[lk+1][r2] = make_float2(pb1.y, pb1.y);
            *(float2*)&Bs[lk+2][r2] = make_float2(pb1.z, pb1.z);
            *(float2*)&Bs[lk+3][r2] = make_float2(pb1.w, pb1.w);
        }
        __syncthreads();
        if (c + 1 < nch) {
            size_t off = (size_t)(c+1) * BKg;
            pa  = *(const float4*)(Ag + off);
            pb0 = *(const float4*)(Wg0 + off);
            if (wb1) pb1 = *(const float4*)(Wg1 + off);
        }
#pragma unroll 8
        for (int kk = 0; kk < BKg; ++kk) {
            ulonglong2 aq = *(const ulonglong2*)&As[kk][4*ty];
            ull am[2] = {aq.x, aq.y};
            ull bd[8];
#pragma unroll
            for (int q = 0; q < 4; q++) {
                ulonglong2 bq = *(const ulonglong2*)&Bs[kk][q*64 + 4*tx];
                bd[2*q]   = bq.x;
                bd[2*q+1] = bq.y;
            }
#pragma unroll
            for (int mp = 0; mp < 2; mp++)
#pragma unroll
                for (int n = 0; n < 8; n++) ffma2(acc[mp][n], am[mp], bd[n]);
        }
    }

    /* epilogue: acc[mp][2q+jj] = (row 2mp, row 2mp+1) at col 32q+2tx+jj */
    const int colb = blockIdx.x * BN;
    float2 bb[4];
#pragma unroll
    for (int q = 0; q < 4; q++)
        bb[q] = *(const float2*)&bias[colb + 32*q + 2*tx];
#pragma unroll
    for (int mp = 0; mp < 2; mp++) {
#pragma unroll
        for (int half = 0; half < 2; half++) {
            int row = blockIdx.y * BM + 4*ty + 2*mp + half;
            float* Cr = C + (size_t)row * N + colb;
#pragma unroll
            for (int q = 0; q < 4; q++) {
                float2 e = upk(acc[mp][2*q]);
                float2 o = upk(acc[mp][2*q+1]);
                float2 v;
                v.x = (half ? e.y : e.x) + bb[q].x;
                v.y = (half ? o.y : o.x) + bb[q].y;
                if (act) { v.x = tanhf(v.x); v.y = tanhf(v.y); }
                *(float2*)&Cr[32*q + 2*tx] = v;
            }
        }
    }
}

/* ================= fused GRU step ========================================
 * Tile 96m x 32j x 3 gates, 384 threads, grid (32, 4) = 128 blocks,
 * 12 warps/block (3 per SMSP) to hide LDS latency under the FFMA2 stream.
 * BK=32 coalesced loads (8 threads per 128B row, 2 passes).
 * Inner loop per kk: 1 a-LDS.128 + 3 b-LDS.128 + 12 FFMA2.               */
#define GRM 96
#define GBK 32
#define GBSTR 204     /* Bs row stride: 4-way store conflict max */

__global__ __launch_bounds__(384) void gru_step(
    const float* __restrict__ h_in, float* __restrict__ h_out,
    const float* __restrict__ gx, const float* __restrict__ W_hh,
    const float* __restrict__ b_hh, float* __restrict__ hid, int t)
{
    __shared__ __align__(16) float As[GBK][ASTR];       /* h, natural   */
    __shared__ __align__(16) float Bs[GBK][GBSTR];      /* W, dup (w,w) */

    const int tid = threadIdx.x;
    const int tx  = tid & 15;          /* col pair: 2tx, 2tx+1 per gate */
    const int ty  = tid >> 4;          /* 0..23: rows 4ty..4ty+3        */
    const int m0  = blockIdx.y * GRM;
    const int j0  = blockIdx.x * 32;

    const int lr8 = tid >> 3;          /* 0..47 */
    const int lk  = (tid & 7) << 2;    /* 0..28 */

    const float* Ag[2];
    const float* Wg[2];
#pragma unroll
    for (int p = 0; p < 2; p++) {
        int ar = p*48 + lr8;                              /* 0..95 */
        Ag[p] = h_in + (size_t)(m0 + ar) * CH + lk;
        int g = ar >> 5, jj = ar & 31;
        Wg[p] = W_hh + (size_t)(g * CH + j0 + jj) * CH + lk;
    }

    ull acc[2][3][2];
#pragma unroll
    for (int i = 0; i < 2; i++)
#pragma unroll
        for (int g = 0; g < 3; g++) { acc[i][g][0] = 0ULL; acc[i][g][1] = 0ULL; }

    float4 pa[2], pb[2];
#pragma unroll
    for (int p = 0; p < 2; p++) {
        pa[p] = *(const float4*)Ag[p];
        pb[p] = *(const float4*)Wg[p];
    }

    const int nch = CH / GBK;   /* 32 */
    for (int c = 0; c < nch; ++c) {
        __syncthreads();
#pragma unroll
        for (int p = 0; p < 2; p++) {
            int ar = p*48 + lr8;
            As[lk+0][ar] = pa[p].x;  As[lk+1][ar] = pa[p].y;
            As[lk+2][ar] = pa[p].z;  As[lk+3][ar] = pa[p].w;
            *(float2*)&Bs[lk+0][2*ar] = make_float2(pb[p].x, pb[p].x);
            *(float2*)&Bs[lk+1][2*ar] = make_float2(pb[p].y, pb[p].y);
            *(float2*)&Bs[lk+2][2*ar] = make_float2(pb[p].z, pb[p].z);
            *(float2*)&Bs[lk+3][2*ar] = make_float2(pb[p].w, pb[p].w);
        }
        __syncthreads();
        if (c + 1 < nch) {
            size_t off = (size_t)(c+1) * GBK;
#pragma unroll
            for (int p = 0; p < 2; p++) {
                pa[p] = *(const float4*)(Ag[p] + off);
                pb[p] = *(const float4*)(Wg[p] + off);
            }
        }
#pragma unroll 8
        for (int kk = 0; kk < GBK; ++kk) {
            ulonglong2 aq = *(const ulonglong2*)&As[kk][4*ty];
            ull am[2] = {aq.x, aq.y};
            ull bd[3][2];
#pragma unroll
            for (int g = 0; g < 3; g++) {
                ulonglong2 bq = *(const ulonglong2*)&Bs[kk][g*64 + 4*tx];
                bd[g][0] = bq.x;
                bd[g][1] = bq.y;
            }
#pragma unroll
            for (int mp = 0; mp < 2; mp++)
#pragma unroll
                for (int g = 0; g < 3; g++) {
                    ffma2(acc[mp][g][0], am[mp], bd[g][0]);
                    ffma2(acc[mp][g][1], am[mp], bd[g][1]);
                }
        }
    }

    /* epilogue: GRU elementwise update (4 m-rows x 2 j-cols per thread) */
    const int jb = j0 + 2*tx;
    float2 bhr = *(const float2*)&b_hh[jb];
    float2 bhz = *(const float2*)&b_hh[CH + jb];
    float2 bhn = *(const float2*)&b_hh[2*CH + jb];
#pragma unroll
    for (int mp = 0; mp < 2; mp++) {
        float2 r0 = upk(acc[mp][0][0]), r1 = upk(acc[mp][0][1]);
        float2 z0 = upk(acc[mp][1][0]), z1 = upk(acc[mp][1][1]);
        float2 n0 = upk(acc[mp][2][0]), n1 = upk(acc[mp][2][1]);
#pragma unroll
        for (int half = 0; half < 2; half++) {
            int m = m0 + 4*ty + 2*mp + half;
            int b = m / CP, p = m - b * CP;
            size_t grow = (size_t)(b * CT + t) * CP + p;
            const float* gxr = gx + grow * (3*CH);
            float2 xr = *(const float2*)&gxr[jb];
            float2 xz = *(const float2*)&gxr[CH + jb];
            float2 xn = *(const float2*)&gxr[2*CH + jb];
            float2 hold = *(const float2*)&h_in[(size_t)m * CH + jb];
            float ghr0 = (half ? r0.y : r0.x) + bhr.x;
            float ghr1 = (half ? r1.y : r1.x) + bhr.y;
            float ghz0 = (half ? z0.y : z0.x) + bhz.x;
            float ghz1 = (half ? z1.y : z1.x) + bhz.y;
            float ghn0 = (half ? n0.y : n0.x) + bhn.x;
            float ghn1 = (half ? n1.y : n1.x) + bhn.y;
            float r_0 = 1.f / (1.f + expf(-(xr.x + ghr0)));
            float r_1 = 1.f / (1.f + expf(-(xr.y + ghr1)));
            float z_0 = 1.f / (1.f + expf(-(xz.x + ghz0)));
            float z_1 = 1.f / (1.f + expf(-(xz.y + ghz1)));
            float n_0 = tanhf(xn.x + r_0 * ghn0);
            float n_1 = tanhf(xn.y + r_1 * ghn1);
            float2 hn;
            hn.x = (1.f - z_0) * n_0 + z_0 * hold.x;
            hn.y = (1.f - z_1) * n_1 + z_1 * hold.y;
            *(float2*)&h_out[(size_t)m * CH + jb] = hn;
            *(float2*)&hid[grow * CH + jb]        = hn;
        }
    }
}

/* ---------------- heads (R7-proven) -------------------------------------- */
__global__ __launch_bounds__(256) void action_head(
    const float* __restrict__ hid, const float* __restrict__ W,
    const float* __restrict__ bias, float* __restrict__ out)
{
    __shared__ float Ws[9 * CH];
    for (int i = threadIdx.x; i < 9 * CH; i += 256) Ws[i] = W[i];
    __syncthreads();
    const int warp = threadIdx.x >> 5, lane = threadIdx.x & 31;
    const int m = blockIdx.x * 8 + warp;
    const float* hr = hid + (size_t)m * CH;
    float p[9];
#pragma unroll
    for (int a = 0; a < 9; a++) p[a] = 0.f;
    for (int kk = 0; kk < CH/32; kk++) {
        int k = lane + 32*kk;
        float v = hr[k];
#pragma unroll
        for (int a = 0; a < 9; a++) p[a] += v * Ws[a*CH + k];
    }
#pragma unroll
    for (int a = 0; a < 9; a++) {
        float s = p[a];
#pragma unroll
        for (int o = 16; o > 0; o >>= 1) s += __shfl_down_sync(0xffffffffu, s, o);
        if (lane == 0) out[(size_t)m * 9 + a] = s + bias[a];
    }
}

__global__ __launch_bounds__(256) void activity_head(
    const float* __restrict__ hid, const float* __restrict__ W,
    const float* __restrict__ bias, float* __restrict__ out)
{
    __shared__ float Ws[8 * CH];
    for (int i = threadIdx.x; i < 8 * CH; i += 256) Ws[i] = W[i];
    __syncthreads();
    const int warp = threadIdx.x >> 5, lane = threadIdx.x & 31;
    const int bt = blockIdx.x * 8 + warp;                 /* (b*T+t) */
    const float* base = hid + (size_t)bt * CP * CH;
    float p[8];
#pragma unroll
    for (int a = 0; a < 8; a++) p[a] = 0.f;
    for (int kk = 0; kk < CH/32; kk++) {
        int k = lane + 32*kk;
        float v = base[k];
#pragma unroll
        for (int pp = 1; pp < CP; pp++) v = fmaxf(v, base[(size_t)pp*CH + k]);
#pragma unroll
        for (int a = 0; a < 8; a++) p[a] += v * Ws[a*CH + k];
    }
#pragma unroll
    for (int a = 0; a < 8; a++) {
        float s = p[a];
#pragma unroll
        for (int o = 16; o > 0; o >>= 1) s += __shfl_down_sync(0xffffffffu, s, o);
        if (lane == 0) out[(size_t)bt * 8 + a] = s + bias[a];
    }
}

__global__ void zero_kernel(float* p, int n) {
    int i = blockIdx.x * 256 + threadIdx.x;
    if (i < n) p[i] = 0.f;
}

/* ---------------- launcher ----------------------------------------------- */
extern "C" void kernel_launch(void* const* d_in, const int* in_sizes, int n_in,
                              void* d_out, int out_size)
{
    const float* feature = (const float*)d_in[0];
    const float* W_embed = (const float*)d_in[1];
    const float* b_embed = (const float*)d_in[2];
    const float* W_ih    = (const float*)d_in[3];
    const float* W_hh    = (const float*)d_in[4];
    const float* b_ih    = (const float*)d_in[5];
    const float* b_hh    = (const float*)d_in[6];
    const float* W_act   = (const float*)d_in[7];
    const float* b_act   = (const float*)d_in[8];
    const float* W_activ = (const float*)d_in[9];
    const float* b_activ = (const float*)d_in[10];
    float* out = (float*)d_out;

    float *px, *pgx, *phid, *ph0, *ph1;
    cudaGetSymbolAddress((void**)&px,   g_x);
    cudaGetSymbolAddress((void**)&pgx,  g_gx);
    cudaGetSymbolAddress((void**)&phid, g_hid);
    cudaGetSymbolAddress((void**)&ph0,  g_h0);
    cudaGetSymbolAddress((void**)&ph1,  g_h1);

    /* h0 = 0 */
    zero_kernel<<<(CBP*CH + 255)/256, 256>>>(ph0, CBP*CH);

    /* x = tanh(feature @ W_embed^T + b_embed)  [15360,1024] */
    gemm_f32x2<<<dim3(CH/BN, CM/BM), 384>>>(feature, W_embed, b_embed, px,
                                            CH, CE, 1);
    /* gx = x @ W_ih^T + b_ih                   [15360,3072] */
    gemm_f32x2<<<dim3(3*CH/BN, CM/BM), 384>>>(px, W_ih, b_ih, pgx,
                                              3*CH, CH, 0);

    /* GRU scan, double-buffered state */
    float* hin = ph0;
    float* hout = ph1;
    for (int t = 0; t < CT; ++t) {
        gru_step<<<dim3(CH/32, CBP/GRM), 384>>>(hin, hout, pgx, W_hh, b_hh,
                                                phid, t);
        float* tmp = hin; hin = hout; hout = tmp;
    }

    /* heads: action logits [15360,9] then activity logits [1280,8] */
    action_head<<<CM/8, 256>>>(phid, W_act, b_act, out);
    activity_head<<<(CB*CT)/8, 256>>>(phid, W_activ, b_activ,
                                      out + (size_t)CM * 9);
}

// round 12
// speedup vs baseline: 1.3644x; 1.3644x over previous
#include <cuda_runtime.h>
#include <math.h>

typedef unsigned long long ull;

#define CB 32
#define CT 40
#define CP 12
#define CE 2048
#define CH 1024
#define CM (CB*CT*CP)     /* 15360 rows of (b,t,p) */
#define CBP (CB*CP)       /* 384 GRU state rows */

/* ---------------- scratch (device globals; no allocation allowed) -------- */
__device__ float g_x  [CM * CH];
__device__ float g_gx [CM * 3 * CH];
__device__ float g_hid[CM * CH];
__device__ float g_h0 [CBP * CH];
__device__ float g_h1 [CBP * CH];

/* ---------------- packed fp32x2 FMA (Blackwell FFMA2) -------------------- */
__device__ __forceinline__ void ffma2(ull& d, ull a, ull b) {
    asm("fma.rn.f32x2 %0, %1, %2, %0;" : "+l"(d) : "l"(a), "l"(b));
}
__device__ __forceinline__ float2 upk(ull v) {
    return *reinterpret_cast<float2*>(&v);
}

/* ================= big GEMM (exact R7 version — proven fastest) ==========
 * C[m,n] = act(A[m,:]·W[n,:] + b[n]); 128x128 tile, BK=8, 256 threads.
 * acc paired along M; A natural smem, W duplicated (w,w).                 */
#define BM 128
#define BN 128
#define BKc 8

__global__ __launch_bounds__(256) void gemm_f32x2(
    const float* __restrict__ A, const float* __restrict__ W,
    const float* __restrict__ bias, float* __restrict__ C,
    int N, int K, int act)
{
    __shared__ __align__(16) float As[BKc][BM + 4];      /* natural      */
    __shared__ __align__(16) float Bs[BKc][2*BN + 8];    /* dup (w,w)    */

    const int tid = threadIdx.x;
    const int tx  = tid & 15;          /* col group            */
    const int ty  = tid >> 4;          /* rows ty*8..ty*8+7    */
    const int lr  = tid >> 1;          /* loader row 0..127    */
    const int lk  = (tid & 1) << 2;    /* loader k offset      */

    const float* Ag = A + (size_t)(blockIdx.y * BM + lr) * K + lk;
    const float* Wg = W + (size_t)(blockIdx.x * BN + lr) * K + lk;

    ull acc[4][8];
#pragma unroll
    for (int i = 0; i < 4; i++)
#pragma unroll
        for (int j = 0; j < 8; j++) acc[i][j] = 0ULL;

    float4 pa = *(const float4*)Ag;
    float4 pb = *(const float4*)Wg;

    const int nch = K / BKc;
    for (int c = 0; c < nch; ++c) {
        __syncthreads();
        As[lk+0][lr] = pa.x;
        As[lk+1][lr] = pa.y;
        As[lk+2][lr] = pa.z;
        As[lk+3][lr] = pa.w;
        *(float2*)&Bs[lk+0][2*lr] = make_float2(pb.x, pb.x);
        *(float2*)&Bs[lk+1][2*lr] = make_float2(pb.y, pb.y);
        *(float2*)&Bs[lk+2][2*lr] = make_float2(pb.z, pb.z);
        *(float2*)&Bs[lk+3][2*lr] = make_float2(pb.w, pb.w);
        __syncthreads();
        if (c + 1 < nch) {                 /* prefetch next chunk to regs */
            pa = *(const float4*)(Ag + (size_t)(c+1)*BKc);
            pb = *(const float4*)(Wg + (size_t)(c+1)*BKc);
        }
#pragma unroll
        for (int kk = 0; kk < BKc; ++kk) {
            ulonglong2 a0 = *(const ulonglong2*)&As[kk][ty*8];
            ulonglong2 a1 = *(const ulonglong2*)&As[kk][ty*8 + 4];
            ull am[4] = {a0.x, a0.y, a1.x, a1.y};
            ull bd[8];
#pragma unroll
            for (int q = 0; q < 4; q++) {
                ulonglong2 bq = *(const ulonglong2*)&Bs[kk][q*64 + 4*tx];
                bd[2*q]   = bq.x;
                bd[2*q+1] = bq.y;
            }
#pragma unroll
            for (int mp = 0; mp < 4; mp++)
#pragma unroll
                for (int n = 0; n < 8; n++) ffma2(acc[mp][n], am[mp], bd[n]);
        }
    }

    /* epilogue: acc[mp][2q+jj] = (row 2mp, row 2mp+1) at col 32q+2tx+jj */
    const int colb = blockIdx.x * BN;
    float2 bb[4];
#pragma unroll
    for (int q = 0; q < 4; q++)
        bb[q] = *(const float2*)&bias[colb + 32*q + 2*tx];
#pragma unroll
    for (int mp = 0; mp < 4; mp++) {
#pragma unroll
        for (int half = 0; half < 2; half++) {
            int row = blockIdx.y * BM + ty*8 + 2*mp + half;
            float* Cr = C + (size_t)row * N + colb;
#pragma unroll
            for (int q = 0; q < 4; q++) {
                float2 e = upk(acc[mp][2*q]);
                float2 o = upk(acc[mp][2*q+1]);
                float2 v;
                v.x = (half ? e.y : e.x) + bb[q].x;
                v.y = (half ? o.y : o.x) + bb[q].y;
                if (act) { v.x = tanhf(v.x); v.y = tanhf(v.y); }
                *(float2*)&Cr[32*q + 2*tx] = v;
            }
        }
    }
}

/* ================= fused GRU step (N-paired, LDS-lean) ===================
 * acc pairs along N: acc[mi][g] = (gh[m][j], gh[m][j+1]). B is NATURAL in
 * smem (LDS.64/gate = 1 wavefront), A is duplicated (h,h) but broadcast
 * (2 distinct addrs/warp -> ~free). Inner loop per kk per warp:
 *   2 a-LDS.128 (2 wf) + 3 b-LDS.64 (3 wf) + 12 FFMA2  -> FFMA2-bound.
 * Tile 48m x (3x32)cols, 192 threads, grid (32,8) = 256 blocks (2/SM).    */
#define GRM 48
#define GBK 16
#define GASTR 100     /* dup-A row stride (2*48=96 used) */
#define GBSTR 100     /* nat-B row stride (96 used)      */

__global__ __launch_bounds__(192) void gru_step(
    const float* __restrict__ h_in, float* __restrict__ h_out,
    const float* __restrict__ gx, const float* __restrict__ W_hh,
    const float* __restrict__ b_hh, float* __restrict__ hid, int t)
{
    __shared__ __align__(16) float As[GBK][GASTR];   /* dup (h,h) pairs */
    __shared__ __align__(16) float Bs[GBK][GBSTR];   /* natural W       */

    const int tid = threadIdx.x;
    const int tx  = tid & 15;          /* cols j0+2tx, j0+2tx+1 per gate */
    const int ty  = tid >> 4;          /* 0..11: rows 4ty..4ty+3         */
    const int m0  = blockIdx.y * GRM;
    const int j0  = blockIdx.x * 32;

    const int alr = tid >> 2;          /* 0..47                  */
    const int alk = (tid & 3) << 2;    /* k offset 0,4,8,12      */

    const float* Ag = h_in + (size_t)(m0 + alr) * CH + alk;
    /* B loader: rows alr and alr+48 of the 96 (gate,col) rows */
    const float* Wg0;
    const float* Wg1;
    {
        int r0 = alr,      g0r = r0 >> 5, j0r = r0 & 31;
        int r1 = alr + 48, g1r = r1 >> 5, j1r = r1 & 31;
        Wg0 = W_hh + (size_t)(g0r * CH + j0 + j0r) * CH + alk;
        Wg1 = W_hh + (size_t)(g1r * CH + j0 + j1r) * CH + alk;
    }

    ull acc[4][3];
#pragma unroll
    for (int i = 0; i < 4; i++)
#pragma unroll
        for (int g = 0; g < 3; g++) acc[i][g] = 0ULL;

    if (t > 0) {    /* t==0: h=0 -> gh=0 (+bias in epilogue), skip GEMM */
        float4 pa  = *(const float4*)Ag;
        float4 pb0 = *(const float4*)Wg0;
        float4 pb1 = *(const float4*)Wg1;

        const int nch = CH / GBK;   /* 64 */
        for (int c = 0; c < nch; ++c) {
            __syncthreads();
            *(float2*)&As[alk+0][2*alr] = make_float2(pa.x, pa.x);
            *(float2*)&As[alk+1][2*alr] = make_float2(pa.y, pa.y);
            *(float2*)&As[alk+2][2*alr] = make_float2(pa.z, pa.z);
            *(float2*)&As[alk+3][2*alr] = make_float2(pa.w, pa.w);
            Bs[alk+0][alr] = pb0.x;  Bs[alk+1][alr] = pb0.y;
            Bs[alk+2][alr] = pb0.z;  Bs[alk+3][alr] = pb0.w;
            Bs[alk+0][alr+48] = pb1.x;  Bs[alk+1][alr+48] = pb1.y;
            Bs[alk+2][alr+48] = pb1.z;  Bs[alk+3][alr+48] = pb1.w;
            __syncthreads();
            if (c + 1 < nch) {
                size_t off = (size_t)(c+1) * GBK;
                pa  = *(const float4*)(Ag + off);
                pb0 = *(const float4*)(Wg0 + off);
                pb1 = *(const float4*)(Wg1 + off);
            }
#pragma unroll
            for (int kk = 0; kk < GBK; ++kk) {
                ulonglong2 a0 = *(const ulonglong2*)&As[kk][8*ty];
                ulonglong2 a1 = *(const ulonglong2*)&As[kk][8*ty + 4];
                ull am[4] = {a0.x, a0.y, a1.x, a1.y};
                ull bg[3];
#pragma unroll
                for (int g = 0; g < 3; g++)
                    bg[g] = *(const ull*)&Bs[kk][g*32 + 2*tx];
#pragma unroll
                for (int mi = 0; mi < 4; mi++)
#pragma unroll
                    for (int g = 0; g < 3; g++)
                        ffma2(acc[mi][g], am[mi], bg[g]);
            }
        }
    }

    /* epilogue: acc[mi][g] = (gh[m][jb], gh[m][jb+1]) — direct float2 math */
    const int jb = j0 + 2*tx;
    const float2 bhr = *(const float2*)&b_hh[jb];
    const float2 bhz = *(const float2*)&b_hh[CH + jb];
    const float2 bhn = *(const float2*)&b_hh[2*CH + jb];
#pragma unroll
    for (int mi = 0; mi < 4; mi++) {
        int m = m0 + 4*ty + mi;
        int b = m / CP, p = m - b * CP;
        size_t grow = (size_t)(b * CT + t) * CP + p;
        const float* gxr = gx + grow * (3*CH);
        float2 gr = upk(acc[mi][0]);
        float2 gz = upk(acc[mi][1]);
        float2 gn = upk(acc[mi][2]);
        float2 xr = *(const float2*)&gxr[jb];
        float2 xz = *(const float2*)&gxr[CH + jb];
        float2 xn = *(const float2*)&gxr[2*CH + jb];
        float2 hold = *(const float2*)&h_in[(size_t)m * CH + jb];
        float r_0 = 1.f / (1.f + expf(-(xr.x + gr.x + bhr.x)));
        float r_1 = 1.f / (1.f + expf(-(xr.y + gr.y + bhr.y)));
        float z_0 = 1.f / (1.f + expf(-(xz.x + gz.x + bhz.x)));
        float z_1 = 1.f / (1.f + expf(-(xz.y + gz.y + bhz.y)));
        float n_0 = tanhf(xn.x + r_0 * (gn.x + bhn.x));
        float n_1 = tanhf(xn.y + r_1 * (gn.y + bhn.y));
        float2 hn;
        hn.x = (1.f - z_0) * n_0 + z_0 * hold.x;
        hn.y = (1.f - z_1) * n_1 + z_1 * hold.y;
        *(float2*)&h_out[(size_t)m * CH + jb] = hn;
        *(float2*)&hid[grow * CH + jb]        = hn;
    }
}

/* ---------------- heads (R7-proven) -------------------------------------- */
__global__ __launch_bounds__(256) void action_head(
    const float* __restrict__ hid, const float* __restrict__ W,
    const float* __restrict__ bias, float* __restrict__ out)
{
    __shared__ float Ws[9 * CH];
    for (int i = threadIdx.x; i < 9 * CH; i += 256) Ws[i] = W[i];
    __syncthreads();
    const int warp = threadIdx.x >> 5, lane = threadIdx.x & 31;
    const int m = blockIdx.x * 8 + warp;
    const float* hr = hid + (size_t)m * CH;
    float p[9];
#pragma unroll
    for (int a = 0; a < 9; a++) p[a] = 0.f;
    for (int kk = 0; kk < CH/32; kk++) {
        int k = lane + 32*kk;
        float v = hr[k];
#pragma unroll
        for (int a = 0; a < 9; a++) p[a] += v * Ws[a*CH + k];
    }
#pragma unroll
    for (int a = 0; a < 9; a++) {
        float s = p[a];
#pragma unroll
        for (int o = 16; o > 0; o >>= 1) s += __shfl_down_sync(0xffffffffu, s, o);
        if (lane == 0) out[(size_t)m * 9 + a] = s + bias[a];
    }
}

__global__ __launch_bounds__(256) void activity_head(
    const float* __restrict__ hid, const float* __restrict__ W,
    const float* __restrict__ bias, float* __restrict__ out)
{
    __shared__ float Ws[8 * CH];
    for (int i = threadIdx.x; i < 8 * CH; i += 256) Ws[i] = W[i];
    __syncthreads();
    const int warp = threadIdx.x >> 5, lane = threadIdx.x & 31;
    const int bt = blockIdx.x * 8 + warp;                 /* (b*T+t) */
    const float* base = hid + (size_t)bt * CP * CH;
    float p[8];
#pragma unroll
    for (int a = 0; a < 8; a++) p[a] = 0.f;
    for (int kk = 0; kk < CH/32; kk++) {
        int k = lane + 32*kk;
        float v = base[k];
#pragma unroll
        for (int pp = 1; pp < CP; pp++) v = fmaxf(v, base[(size_t)pp*CH + k]);
#pragma unroll
        for (int a = 0; a < 8; a++) p[a] += v * Ws[a*CH + k];
    }
#pragma unroll
    for (int a = 0; a < 8; a++) {
        float s = p[a];
#pragma unroll
        for (int o = 16; o > 0; o >>= 1) s += __shfl_down_sync(0xffffffffu, s, o);
        if (lane == 0) out[(size_t)bt * 8 + a] = s + bias[a];
    }
}

__global__ void zero_kernel(float* p, int n) {
    int i = blockIdx.x * 256 + threadIdx.x;
    if (i < n) p[i] = 0.f;
}

/* ---------------- launcher ----------------------------------------------- */
extern "C" void kernel_launch(void* const* d_in, const int* in_sizes, int n_in,
                              void* d_out, int out_size)
{
    const float* feature = (const float*)d_in[0];
    const float* W_embed = (const float*)d_in[1];
    const float* b_embed = (const float*)d_in[2];
    const float* W_ih    = (const float*)d_in[3];
    const float* W_hh    = (const float*)d_in[4];
    const float* b_ih    = (const float*)d_in[5];
    const float* b_hh    = (const float*)d_in[6];
    const float* W_act   = (const float*)d_in[7];
    const float* b_act   = (const float*)d_in[8];
    const float* W_activ = (const float*)d_in[9];
    const float* b_activ = (const float*)d_in[10];
    float* out = (float*)d_out;

    float *px, *pgx, *phid, *ph0, *ph1;
    cudaGetSymbolAddress((void**)&px,   g_x);
    cudaGetSymbolAddress((void**)&pgx,  g_gx);
    cudaGetSymbolAddress((void**)&phid, g_hid);
    cudaGetSymbolAddress((void**)&ph0,  g_h0);
    cudaGetSymbolAddress((void**)&ph1,  g_h1);

    /* h0 = 0 */
    zero_kernel<<<(CBP*CH + 255)/256, 256>>>(ph0, CBP*CH);

    /* x = tanh(feature @ W_embed^T + b_embed)  [15360,1024] */
    gemm_f32x2<<<dim3(CH/BN, CM/BM), 256>>>(feature, W_embed, b_embed, px,
                                            CH, CE, 1);
    /* gx = x @ W_ih^T + b_ih                   [15360,3072] */
    gemm_f32x2<<<dim3(3*CH/BN, CM/BM), 256>>>(px, W_ih, b_ih, pgx,
                                              3*CH, CH, 0);

    /* GRU scan, double-buffered state */
    float* hin = ph0;
    float* hout = ph1;
    for (int t = 0; t < CT; ++t) {
        gru_step<<<dim3(CH/32, CBP/GRM), 192>>>(hin, hout, pgx, W_hh, b_hh,
                                                phid, t);
        float* tmp = hin; hin = hout; hout = tmp;
    }

    /* heads: action logits [15360,9] then activity logits [1280,8] */
    action_head<<<CM/8, 256>>>(phid, W_act, b_act, out);
    activity_head<<<(CB*CT)/8, 256>>>(phid, W_activ, b_activ,
                                      out + (size_t)CM * 9);
}

// round 15
// speedup vs baseline: 1.7646x; 1.2933x over previous
#include <cuda_runtime.h>
#include <cuda_bf16.h>
#include <mma.h>
#include <stdint.h>
#include <math.h>

using namespace nvcuda;

typedef unsigned long long ull;

#define CB 32
#define CT 40
#define CP 12
#define CE 2048
#define CH 1024
#define CM (CB*CT*CP)     /* 15360 rows of (b,t,p) */
#define CBP (CB*CP)       /* 384 GRU state rows */

/* ---------------- scratch (device globals; no allocation allowed) -------- */
__device__ float g_gx [CM * 3 * CH];    /* input gates (fp32)    */
__device__ float g_xf [CM * CH];        /* embed raw fp32        */
__device__ float g_hid[CM * CH];        /* all hiddens           */
__device__ float g_h0 [CBP * CH];
__device__ float g_h1 [CBP * CH];
/* bf16 hi/lo operands for tensor-core GEMMs */
__device__ __nv_bfloat16 g_fh [CM * CE];
__device__ __nv_bfloat16 g_fl [CM * CE];
__device__ __nv_bfloat16 g_xh [CM * CH];
__device__ __nv_bfloat16 g_xl [CM * CH];
__device__ __nv_bfloat16 g_Weh[CH * CE];
__device__ __nv_bfloat16 g_Wel[CH * CE];
__device__ __nv_bfloat16 g_Wih[3 * CH * CH];
__device__ __nv_bfloat16 g_Wil[3 * CH * CH];

/* ---------------- packed fp32x2 FMA (scan) -------------------------------- */
__device__ __forceinline__ void ffma2(ull& d, ull a, ull b) {
    asm("fma.rn.f32x2 %0, %1, %2, %0;" : "+l"(d) : "l"(a), "l"(b));
}
__device__ __forceinline__ float2 upk(ull v) {
    return *reinterpret_cast<float2*>(&v);
}

/* ================= tensor-core GEMM via wmma (bf16 hi/lo split) ==========
 * Craw[m,n] = A[m,:]·W[n,:]  (fp32, bias added by epilogue kernels).
 * Block 128x128, 8 warps (warp tile 64x32 = 4x2 wmma frags), Kc=32.
 * Hi/lo split: A·B ~= AhBh + AhBl + AlBh (fp32 accum; err <= 2^-18 rel).
 * Smem tiles padded to 40 halves/row (80B -> conflict-free ldmatrix).    */
#define WTS 40

__global__ __launch_bounds__(256) void gemm_wmma(
    const __nv_bfloat16* __restrict__ Ah, const __nv_bfloat16* __restrict__ Al,
    const __nv_bfloat16* __restrict__ Bh, const __nv_bfloat16* __restrict__ Bl,
    float* __restrict__ Craw, int N, int K)
{
    __shared__ __align__(16) __nv_bfloat16 sAh[128*WTS];
    __shared__ __align__(16) __nv_bfloat16 sAl[128*WTS];
    __shared__ __align__(16) __nv_bfloat16 sBh[128*WTS];
    __shared__ __align__(16) __nv_bfloat16 sBl[128*WTS];

    const int tid = threadIdx.x, wid = tid >> 5;
    const int m0 = blockIdx.y * 128, n0 = blockIdx.x * 128;
    const int wm = wid & 1;            /* 0..1: warp m-offset 64*wm */
    const int wn = wid >> 1;           /* 0..3: warp n-offset 32*wn */

    wmma::fragment<wmma::accumulator, 16, 16, 16, float> acc[4][2];
#pragma unroll
    for (int i = 0; i < 4; i++)
#pragma unroll
        for (int j = 0; j < 2; j++) wmma::fill_fragment(acc[i][j], 0.0f);

    const int lrow = tid >> 2;          /* loader row 0..63 (2 passes) */
    const int lc4  = tid & 3;           /* 16B chunk within 64B row    */

    const int nch = K / 32;
    for (int c = 0; c < nch; ++c) {
        const int k0 = c * 32;
        __syncthreads();
#pragma unroll
        for (int r = 0; r < 2; ++r) {
            int rr = lrow + r * 64;
            size_t ga = (size_t)(m0 + rr) * K + k0 + lc4 * 8;
            size_t gb = (size_t)(n0 + rr) * K + k0 + lc4 * 8;
            int so = rr * WTS + lc4 * 8;
            *(uint4*)&sAh[so] = *(const uint4*)&Ah[ga];
            *(uint4*)&sAl[so] = *(const uint4*)&Al[ga];
            *(uint4*)&sBh[so] = *(const uint4*)&Bh[gb];
            *(uint4*)&sBl[so] = *(const uint4*)&Bl[gb];
        }
        __syncthreads();
#pragma unroll
        for (int ks = 0; ks < 32; ks += 16) {
            wmma::fragment<wmma::matrix_a, 16, 16, 16, __nv_bfloat16,
                           wmma::row_major> ah[4], al[4];
            wmma::fragment<wmma::matrix_b, 16, 16, 16, __nv_bfloat16,
                           wmma::col_major> bh[2], bl[2];
#pragma unroll
            for (int i = 0; i < 4; i++) {
                wmma::load_matrix_sync(ah[i], &sAh[(wm*64 + i*16)*WTS + ks], WTS);
                wmma::load_matrix_sync(al[i], &sAl[(wm*64 + i*16)*WTS + ks], WTS);
            }
#pragma unroll
            for (int j = 0; j < 2; j++) {
                wmma::load_matrix_sync(bh[j], &sBh[(wn*32 + j*16)*WTS + ks], WTS);
                wmma::load_matrix_sync(bl[j], &sBl[(wn*32 + j*16)*WTS + ks], WTS);
            }
#pragma unroll
            for (int i = 0; i < 4; i++)
#pragma unroll
                for (int j = 0; j < 2; j++) {
                    wmma::mma_sync(acc[i][j], ah[i], bh[j], acc[i][j]);
                    wmma::mma_sync(acc[i][j], ah[i], bl[j], acc[i][j]);
                    wmma::mma_sync(acc[i][j], al[i], bh[j], acc[i][j]);
                }
        }
    }

#pragma unroll
    for (int i = 0; i < 4; i++)
#pragma unroll
        for (int j = 0; j < 2; j++)
            wmma::store_matrix_sync(
                &Craw[(size_t)(m0 + wm*64 + i*16) * N + n0 + wn*32 + j*16],
                acc[i][j], N, wmma::mem_row_major);
}

/* ---------------- GEMM epilogues ------------------------------------------ */
/* gx += bias (in place), grid (N/256, M) */
__global__ __launch_bounds__(256) void bias2d(
    float* __restrict__ C, const float* __restrict__ bias, int N)
{
    int col = blockIdx.x * 256 + threadIdx.x;
    C[(size_t)blockIdx.y * N + col] += bias[col];
}

/* x = tanh(raw + bias) -> bf16 hi/lo, grid (CH/256, CM) */
__global__ __launch_bounds__(256) void tanh_hilo(
    const float* __restrict__ raw, const float* __restrict__ bias,
    __nv_bfloat16* __restrict__ hi, __nv_bfloat16* __restrict__ lo)
{
    int col = blockIdx.x * 256 + threadIdx.x;
    size_t i = (size_t)blockIdx.y * CH + col;
    float v = tanhf(raw[i] + bias[col]);
    __nv_bfloat16 h = __float2bfloat16(v);
    hi[i] = h;
    lo[i] = __float2bfloat16(v - __bfloat162float(h));
}

/* ---------------- fp32 -> bf16 hi/lo conversion -------------------------- */
__global__ __launch_bounds__(256) void cvt_hilo(
    const float* __restrict__ src, __nv_bfloat16* __restrict__ hi,
    __nv_bfloat16* __restrict__ lo, int n)
{
    int i = blockIdx.x * 256 + threadIdx.x;
    if (i >= n) return;
    float v = src[i];
    __nv_bfloat16 h = __float2bfloat16(v);
    hi[i] = h;
    lo[i] = __float2bfloat16(v - __bfloat162float(h));
}

/* ================= fused GRU step (R12-proven, N-paired) ================= */
#define GRM 48
#define GBK 16
#define GASTR 100
#define GBSTR 100

__global__ __launch_bounds__(192) void gru_step(
    const float* __restrict__ h_in, float* __restrict__ h_out,
    const float* __restrict__ gx, const float* __restrict__ W_hh,
    const float* __restrict__ b_hh, float* __restrict__ hid, int t)
{
    __shared__ __align__(16) float As[GBK][GASTR];
    __shared__ __align__(16) float Bs[GBK][GBSTR];

    const int tid = threadIdx.x;
    const int tx  = tid & 15;
    const int ty  = tid >> 4;
    const int m0  = blockIdx.y * GRM;
    const int j0  = blockIdx.x * 32;

    const int alr = tid >> 2;
    const int alk = (tid & 3) << 2;

    const float* Ag = h_in + (size_t)(m0 + alr) * CH + alk;
    const float* Wg0;
    const float* Wg1;
    {
        int r0 = alr,      g0r = r0 >> 5, j0r = r0 & 31;
        int r1 = alr + 48, g1r = r1 >> 5, j1r = r1 & 31;
        Wg0 = W_hh + (size_t)(g0r * CH + j0 + j0r) * CH + alk;
        Wg1 = W_hh + (size_t)(g1r * CH + j0 + j1r) * CH + alk;
    }

    ull acc[4][3];
#pragma unroll
    for (int i = 0; i < 4; i++)
#pragma unroll
        for (int g = 0; g < 3; g++) acc[i][g] = 0ULL;

    if (t > 0) {
        float4 pa  = *(const float4*)Ag;
        float4 pb0 = *(const float4*)Wg0;
        float4 pb1 = *(const float4*)Wg1;

        const int nch = CH / GBK;
        for (int c = 0; c < nch; ++c) {
            __syncthreads();
            *(float2*)&As[alk+0][2*alr] = make_float2(pa.x, pa.x);
            *(float2*)&As[alk+1][2*alr] = make_float2(pa.y, pa.y);
            *(float2*)&As[alk+2][2*alr] = make_float2(pa.z, pa.z);
            *(float2*)&As[alk+3][2*alr] = make_float2(pa.w, pa.w);
            Bs[alk+0][alr] = pb0.x;  Bs[alk+1][alr] = pb0.y;
            Bs[alk+2][alr] = pb0.z;  Bs[alk+3][alr] = pb0.w;
            Bs[alk+0][alr+48] = pb1.x;  Bs[alk+1][alr+48] = pb1.y;
            Bs[alk+2][alr+48] = pb1.z;  Bs[alk+3][alr+48] = pb1.w;
            __syncthreads();
            if (c + 1 < nch) {
                size_t off = (size_t)(c+1) * GBK;
                pa  = *(const float4*)(Ag + off);
                pb0 = *(const float4*)(Wg0 + off);
                pb1 = *(const float4*)(Wg1 + off);
            }
#pragma unroll
            for (int kk = 0; kk < GBK; ++kk) {
                ulonglong2 a0 = *(const ulonglong2*)&As[kk][8*ty];
                ulonglong2 a1 = *(const ulonglong2*)&As[kk][8*ty + 4];
                ull am[4] = {a0.x, a0.y, a1.x, a1.y};
                ull bg[3];
#pragma unroll
                for (int g = 0; g < 3; g++)
                    bg[g] = *(const ull*)&Bs[kk][g*32 + 2*tx];
#pragma unroll
                for (int mi = 0; mi < 4; mi++)
#pragma unroll
                    for (int g = 0; g < 3; g++)
                        ffma2(acc[mi][g], am[mi], bg[g]);
            }
        }
    }

    const int jb = j0 + 2*tx;
    const float2 bhr = *(const float2*)&b_hh[jb];
    const float2 bhz = *(const float2*)&b_hh[CH + jb];
    const float2 bhn = *(const float2*)&b_hh[2*CH + jb];
#pragma unroll
    for (int mi = 0; mi < 4; mi++) {
        int m = m0 + 4*ty + mi;
        int b = m / CP, p = m - b * CP;
        size_t grow = (size_t)(b * CT + t) * CP + p;
        const float* gxr = gx + grow * (3*CH);
        float2 gr = upk(acc[mi][0]);
        float2 gz = upk(acc[mi][1]);
        float2 gn = upk(acc[mi][2]);
        float2 xr = *(const float2*)&gxr[jb];
        float2 xz = *(const float2*)&gxr[CH + jb];
        float2 xn = *(const float2*)&gxr[2*CH + jb];
        float2 hold = *(const float2*)&h_in[(size_t)m * CH + jb];
        float r_0 = 1.f / (1.f + expf(-(xr.x + gr.x + bhr.x)));
        float r_1 = 1.f / (1.f + expf(-(xr.y + gr.y + bhr.y)));
        float z_0 = 1.f / (1.f + expf(-(xz.x + gz.x + bhz.x)));
        float z_1 = 1.f / (1.f + expf(-(xz.y + gz.y + bhz.y)));
        float n_0 = tanhf(xn.x + r_0 * (gn.x + bhn.x));
        float n_1 = tanhf(xn.y + r_1 * (gn.y + bhn.y));
        float2 hn;
        hn.x = (1.f - z_0) * n_0 + z_0 * hold.x;
        hn.y = (1.f - z_1) * n_1 + z_1 * hold.y;
        *(float2*)&h_out[(size_t)m * CH + jb] = hn;
        *(float2*)&hid[grow * CH + jb]        = hn;
    }
}

/* ---------------- heads (R7-proven) -------------------------------------- */
__global__ __launch_bounds__(256) void action_head(
    const float* __restrict__ hid, const float* __restrict__ W,
    const float* __restrict__ bias, float* __restrict__ out)
{
    __shared__ float Ws[9 * CH];
    for (int i = threadIdx.x; i < 9 * CH; i += 256) Ws[i] = W[i];
    __syncthreads();
    const int warp = threadIdx.x >> 5, lane = threadIdx.x & 31;
    const int m = blockIdx.x * 8 + warp;
    const float* hr = hid + (size_t)m * CH;
    float p[9];
#pragma unroll
    for (int a = 0; a < 9; a++) p[a] = 0.f;
    for (int kk = 0; kk < CH/32; kk++) {
        int k = lane + 32*kk;
        float v = hr[k];
#pragma unroll
        for (int a = 0; a < 9; a++) p[a] += v * Ws[a*CH + k];
    }
#pragma unroll
    for (int a = 0; a < 9; a++) {
        float s = p[a];
#pragma unroll
        for (int o = 16; o > 0; o >>= 1) s += __shfl_down_sync(0xffffffffu, s, o);
        if (lane == 0) out[(size_t)m * 9 + a] = s + bias[a];
    }
}

__global__ __launch_bounds__(256) void activity_head(
    const float* __restrict__ hid, const float* __restrict__ W,
    const float* __restrict__ bias, float* __restrict__ out)
{
    __shared__ float Ws[8 * CH];
    for (int i = threadIdx.x; i < 8 * CH; i += 256) Ws[i] = W[i];
    __syncthreads();
    const int warp = threadIdx.x >> 5, lane = threadIdx.x & 31;
    const int bt = blockIdx.x * 8 + warp;
    const float* base = hid + (size_t)bt * CP * CH;
    float p[8];
#pragma unroll
    for (int a = 0; a < 8; a++) p[a] = 0.f;
    for (int kk = 0; kk < CH/32; kk++) {
        int k = lane + 32*kk;
        float v = base[k];
#pragma unroll
        for (int pp = 1; pp < CP; pp++) v = fmaxf(v, base[(size_t)pp*CH + k]);
#pragma unroll
        for (int a = 0; a < 8; a++) p[a] += v * Ws[a*CH + k];
    }
#pragma unroll
    for (int a = 0; a < 8; a++) {
        float s = p[a];
#pragma unroll
        for (int o = 16; o > 0; o >>= 1) s += __shfl_down_sync(0xffffffffu, s, o);
        if (lane == 0) out[(size_t)bt * 8 + a] = s + bias[a];
    }
}

__global__ void zero_kernel(float* p, int n) {
    int i = blockIdx.x * 256 + threadIdx.x;
    if (i < n) p[i] = 0.f;
}

/* ---------------- launcher ----------------------------------------------- */
extern "C" void kernel_launch(void* const* d_in, const int* in_sizes, int n_in,
                              void* d_out, int out_size)
{
    const float* feature = (const float*)d_in[0];
    const float* W_embed = (const float*)d_in[1];
    const float* b_embed = (const float*)d_in[2];
    const float* W_ih    = (const float*)d_in[3];
    const float* W_hh    = (const float*)d_in[4];
    const float* b_ih    = (const float*)d_in[5];
    const float* b_hh    = (const float*)d_in[6];
    const float* W_act   = (const float*)d_in[7];
    const float* b_act   = (const float*)d_in[8];
    const float* W_activ = (const float*)d_in[9];
    const float* b_activ = (const float*)d_in[10];
    float* out = (float*)d_out;

    float *pgx, *pxf, *phid, *ph0, *ph1;
    __nv_bfloat16 *pfh, *pfl, *pxh, *pxl, *pWeh, *pWel, *pWih, *pWil;
    cudaGetSymbolAddress((void**)&pgx,  g_gx);
    cudaGetSymbolAddress((void**)&pxf,  g_xf);
    cudaGetSymbolAddress((void**)&phid, g_hid);
    cudaGetSymbolAddress((void**)&ph0,  g_h0);
    cudaGetSymbolAddress((void**)&ph1,  g_h1);
    cudaGetSymbolAddress((void**)&pfh,  g_fh);
    cudaGetSymbolAddress((void**)&pfl,  g_fl);
    cudaGetSymbolAddress((void**)&pxh,  g_xh);
    cudaGetSymbolAddress((void**)&pxl,  g_xl);
    cudaGetSymbolAddress((void**)&pWeh, g_Weh);
    cudaGetSymbolAddress((void**)&pWel, g_Wel);
    cudaGetSymbolAddress((void**)&pWih, g_Wih);
    cudaGetSymbolAddress((void**)&pWil, g_Wil);

    /* h0 = 0 */
    zero_kernel<<<(CBP*CH + 255)/256, 256>>>(ph0, CBP*CH);

    /* fp32 -> bf16 hi/lo conversions */
    cvt_hilo<<<(CM*CE + 255)/256, 256>>>(feature, pfh, pfl, CM*CE);
    cvt_hilo<<<(CH*CE + 255)/256, 256>>>(W_embed, pWeh, pWel, CH*CE);
    cvt_hilo<<<(3*CH*CH + 255)/256, 256>>>(W_ih, pWih, pWil, 3*CH*CH);

    /* xraw = feature @ W_embed^T ; x = tanh(xraw + b) -> bf16 hi/lo */
    gemm_wmma<<<dim3(CH/128, CM/128), 256>>>(pfh, pfl, pWeh, pWel, pxf,
                                             CH, CE);
    tanh_hilo<<<dim3(CH/256, CM), 256>>>(pxf, b_embed, pxh, pxl);

    /* gx = x @ W_ih^T + b_ih  (fp32) */
    gemm_wmma<<<dim3(3*CH/128, CM/128), 256>>>(pxh, pxl, pWih, pWil, pgx,
                                               3*CH, CH);
    bias2d<<<dim3(3*CH/256, CM), 256>>>(pgx, b_ih, 3*CH);

    /* GRU scan, double-buffered state (R12-proven) */
    float* hin = ph0;
    float* hout = ph1;
    for (int t = 0; t < CT; ++t) {
        gru_step<<<dim3(CH/32, CBP/GRM), 192>>>(hin, hout, pgx, W_hh, b_hh,
                                                phid, t);
        float* tmp = hin; hin = hout; hout = tmp;
    }

    /* heads: action logits [15360,9] then activity logits [1280,8] */
    action_head<<<CM/8, 256>>>(phid, W_act, b_act, out);
    activity_head<<<(CB*CT)/8, 256>>>(phid, W_activ, b_activ,
                                      out + (size_t)CM * 9);
}

// round 16
// speedup vs baseline: 2.1532x; 1.2202x over previous
#include <cuda_runtime.h>
#include <cuda_bf16.h>
#include <mma.h>
#include <stdint.h>
#include <math.h>

using namespace nvcuda;

typedef unsigned long long ull;

#define CB 32
#define CT 40
#define CP 12
#define CE 2048
#define CH 1024
#define CM (CB*CT*CP)     /* 15360 rows of (b,t,p) */
#define CBP (CB*CP)       /* 384 GRU state rows */

/* ---------------- scratch (device globals; no allocation allowed) -------- */
__device__ float g_gx [CM * 3 * CH];    /* input gates (fp32)    */
__device__ float g_xf [CM * CH];        /* embed raw fp32        */
__device__ float g_hid[CM * CH];        /* all hiddens           */
__device__ float g_h0 [CBP * CH];       /* h state fp32, dbl-buf */
__device__ float g_h1 [CBP * CH];
__device__ __nv_bfloat16 g_hh0[CBP * CH];  /* h hi/lo, dbl-buf   */
__device__ __nv_bfloat16 g_hl0[CBP * CH];
__device__ __nv_bfloat16 g_hh1[CBP * CH];
__device__ __nv_bfloat16 g_hl1[CBP * CH];
/* bf16 hi/lo operands for tensor-core GEMMs */
__device__ __nv_bfloat16 g_fh [CM * CE];
__device__ __nv_bfloat16 g_fl [CM * CE];
__device__ __nv_bfloat16 g_xh [CM * CH];
__device__ __nv_bfloat16 g_xl [CM * CH];
__device__ __nv_bfloat16 g_Weh[CH * CE];
__device__ __nv_bfloat16 g_Wel[CH * CE];
__device__ __nv_bfloat16 g_Wih[3 * CH * CH];
__device__ __nv_bfloat16 g_Wil[3 * CH * CH];
__device__ __nv_bfloat16 g_Whh[3 * CH * CH];
__device__ __nv_bfloat16 g_Whl[3 * CH * CH];

/* ================= tensor-core GEMM via wmma (R15-proven) ================ */
#define WTS 40

__global__ __launch_bounds__(256) void gemm_wmma(
    const __nv_bfloat16* __restrict__ Ah, const __nv_bfloat16* __restrict__ Al,
    const __nv_bfloat16* __restrict__ Bh, const __nv_bfloat16* __restrict__ Bl,
    float* __restrict__ Craw, int N, int K)
{
    __shared__ __align__(16) __nv_bfloat16 sAh[128*WTS];
    __shared__ __align__(16) __nv_bfloat16 sAl[128*WTS];
    __shared__ __align__(16) __nv_bfloat16 sBh[128*WTS];
    __shared__ __align__(16) __nv_bfloat16 sBl[128*WTS];

    const int tid = threadIdx.x, wid = tid >> 5;
    const int m0 = blockIdx.y * 128, n0 = blockIdx.x * 128;
    const int wm = wid & 1;
    const int wn = wid >> 1;

    wmma::fragment<wmma::accumulator, 16, 16, 16, float> acc[4][2];
#pragma unroll
    for (int i = 0; i < 4; i++)
#pragma unroll
        for (int j = 0; j < 2; j++) wmma::fill_fragment(acc[i][j], 0.0f);

    const int lrow = tid >> 2;
    const int lc4  = tid & 3;

    const int nch = K / 32;
    for (int c = 0; c < nch; ++c) {
        const int k0 = c * 32;
        __syncthreads();
#pragma unroll
        for (int r = 0; r < 2; ++r) {
            int rr = lrow + r * 64;
            size_t ga = (size_t)(m0 + rr) * K + k0 + lc4 * 8;
            size_t gb = (size_t)(n0 + rr) * K + k0 + lc4 * 8;
            int so = rr * WTS + lc4 * 8;
            *(uint4*)&sAh[so] = *(const uint4*)&Ah[ga];
            *(uint4*)&sAl[so] = *(const uint4*)&Al[ga];
            *(uint4*)&sBh[so] = *(const uint4*)&Bh[gb];
            *(uint4*)&sBl[so] = *(const uint4*)&Bl[gb];
        }
        __syncthreads();
#pragma unroll
        for (int ks = 0; ks < 32; ks += 16) {
            wmma::fragment<wmma::matrix_a, 16, 16, 16, __nv_bfloat16,
                           wmma::row_major> ah[4], al[4];
            wmma::fragment<wmma::matrix_b, 16, 16, 16, __nv_bfloat16,
                           wmma::col_major> bh[2], bl[2];
#pragma unroll
            for (int i = 0; i < 4; i++) {
                wmma::load_matrix_sync(ah[i], &sAh[(wm*64 + i*16)*WTS + ks], WTS);
                wmma::load_matrix_sync(al[i], &sAl[(wm*64 + i*16)*WTS + ks], WTS);
            }
#pragma unroll
            for (int j = 0; j < 2; j++) {
                wmma::load_matrix_sync(bh[j], &sBh[(wn*32 + j*16)*WTS + ks], WTS);
                wmma::load_matrix_sync(bl[j], &sBl[(wn*32 + j*16)*WTS + ks], WTS);
            }
#pragma unroll
            for (int i = 0; i < 4; i++)
#pragma unroll
                for (int j = 0; j < 2; j++) {
                    wmma::mma_sync(acc[i][j], ah[i], bh[j], acc[i][j]);
                    wmma::mma_sync(acc[i][j], ah[i], bl[j], acc[i][j]);
                    wmma::mma_sync(acc[i][j], al[i], bh[j], acc[i][j]);
                }
        }
    }

#pragma unroll
    for (int i = 0; i < 4; i++)
#pragma unroll
        for (int j = 0; j < 2; j++)
            wmma::store_matrix_sync(
                &Craw[(size_t)(m0 + wm*64 + i*16) * N + n0 + wn*32 + j*16],
                acc[i][j], N, wmma::mem_row_major);
}

/* ---------------- GEMM epilogues ------------------------------------------ */
__global__ __launch_bounds__(256) void bias2d(
    float* __restrict__ C, const float* __restrict__ bias, int N)
{
    int col = blockIdx.x * 256 + threadIdx.x;
    C[(size_t)blockIdx.y * N + col] += bias[col];
}

__global__ __launch_bounds__(256) void tanh_hilo(
    const float* __restrict__ raw, const float* __restrict__ bias,
    __nv_bfloat16* __restrict__ hi, __nv_bfloat16* __restrict__ lo)
{
    int col = blockIdx.x * 256 + threadIdx.x;
    size_t i = (size_t)blockIdx.y * CH + col;
    float v = tanhf(raw[i] + bias[col]);
    __nv_bfloat16 h = __float2bfloat16(v);
    hi[i] = h;
    lo[i] = __float2bfloat16(v - __bfloat162float(h));
}

__global__ __launch_bounds__(256) void cvt_hilo(
    const float* __restrict__ src, __nv_bfloat16* __restrict__ hi,
    __nv_bfloat16* __restrict__ lo, int n)
{
    int i = blockIdx.x * 256 + threadIdx.x;
    if (i >= n) return;
    float v = src[i];
    __nv_bfloat16 h = __float2bfloat16(v);
    hi[i] = h;
    lo[i] = __float2bfloat16(v - __bfloat162float(h));
}

/* ================= tensor-core GRU step ==================================
 * gh = h_in · W_hh^T via wmma hi/lo (AhBh+AhBl+AlBh), then fused GRU
 * update. Block: 64 m x (3 gates x 32 j) = 64x96 output; grid (32,6)=192.
 * 8 warps, warp tile 16m x 48n (3 frags). K=1024, Kc=32 chunks.
 * Accs staged through smem (64x100 f32, reusing operand buffers) so the
 * elementwise epilogue reads gh at known coords. Epilogue writes h fp32 +
 * bf16 hi/lo (consumed by next step's MMA) + hid.                         */
__global__ __launch_bounds__(256) void gru_step_tc(
    const float* __restrict__ h_in,
    const __nv_bfloat16* __restrict__ hh_in,
    const __nv_bfloat16* __restrict__ hl_in,
    float* __restrict__ h_out,
    __nv_bfloat16* __restrict__ hh_out,
    __nv_bfloat16* __restrict__ hl_out,
    const float* __restrict__ gx,
    const __nv_bfloat16* __restrict__ Wh,
    const __nv_bfloat16* __restrict__ Wl,
    const float* __restrict__ b_hh, float* __restrict__ hid, int t)
{
    __shared__ __align__(16) char sbuf[25600];
    __nv_bfloat16* sAh = (__nv_bfloat16*)(sbuf);           /* 64x40  */
    __nv_bfloat16* sAl = (__nv_bfloat16*)(sbuf + 5120);    /* 64x40  */
    __nv_bfloat16* sBh = (__nv_bfloat16*)(sbuf + 10240);   /* 96x40  */
    __nv_bfloat16* sBl = (__nv_bfloat16*)(sbuf + 17920);   /* 96x40  */
    float*         sgh = (float*)(sbuf);                   /* 64x100 */

    const int tid = threadIdx.x, wid = tid >> 5;
    const int m0 = blockIdx.y * 64, j0 = blockIdx.x * 32;
    const int wm = wid & 3;           /* m-group: rows wm*16..+15   */
    const int wn = wid >> 2;          /* n-group: cols wn*48..+47   */

    wmma::fragment<wmma::accumulator, 16, 16, 16, float> acc[3];
#pragma unroll
    for (int f = 0; f < 3; f++) wmma::fill_fragment(acc[f], 0.0f);

    if (t > 0) {
        const int lr = tid >> 2;        /* 0..63 */
        const int lc = (tid & 3) * 8;   /* 16B chunk */
        /* B row r (0..95): gate r>>5, col j0 + (r&31) */
        const int g1 = (64 + lr) >> 5, j1 = (64 + lr) & 31;   /* pass2, lr<32 */
        const int g0 = lr >> 5,        jj0 = lr & 31;

        for (int c = 0; c < 32; ++c) {
            const int k0 = c * 32;
            __syncthreads();
            {
                size_t ga = (size_t)(m0 + lr) * CH + k0 + lc;
                int so = lr * WTS + lc;
                *(uint4*)&sAh[so] = *(const uint4*)&hh_in[ga];
                *(uint4*)&sAl[so] = *(const uint4*)&hl_in[ga];
                size_t gb = (size_t)(g0 * CH + j0 + jj0) * CH + k0 + lc;
                *(uint4*)&sBh[so] = *(const uint4*)&Wh[gb];
                *(uint4*)&sBl[so] = *(const uint4*)&Wl[gb];
                if (lr < 32) {
                    size_t gb1 = (size_t)(g1 * CH + j0 + j1) * CH + k0 + lc;
                    int so1 = (64 + lr) * WTS + lc;
                    *(uint4*)&sBh[so1] = *(const uint4*)&Wh[gb1];
                    *(uint4*)&sBl[so1] = *(const uint4*)&Wl[gb1];
                }
            }
            __syncthreads();
#pragma unroll
            for (int ks = 0; ks < 32; ks += 16) {
                wmma::fragment<wmma::matrix_a, 16, 16, 16, __nv_bfloat16,
                               wmma::row_major> ah, al;
                wmma::fragment<wmma::matrix_b, 16, 16, 16, __nv_bfloat16,
                               wmma::col_major> bh[3], bl[3];
                wmma::load_matrix_sync(ah, &sAh[(wm*16)*WTS + ks], WTS);
                wmma::load_matrix_sync(al, &sAl[(wm*16)*WTS + ks], WTS);
#pragma unroll
                for (int f = 0; f < 3; f++) {
                    wmma::load_matrix_sync(bh[f], &sBh[(wn*48 + f*16)*WTS + ks], WTS);
                    wmma::load_matrix_sync(bl[f], &sBl[(wn*48 + f*16)*WTS + ks], WTS);
                }
#pragma unroll
                for (int f = 0; f < 3; f++) {
                    wmma::mma_sync(acc[f], ah, bh[f], acc[f]);
                    wmma::mma_sync(acc[f], ah, bl[f], acc[f]);
                    wmma::mma_sync(acc[f], al, bh[f], acc[f]);
                }
            }
        }
    }

    /* stage gh through smem (reuses operand buffers) */
    __syncthreads();
#pragma unroll
    for (int f = 0; f < 3; f++)
        wmma::store_matrix_sync(&sgh[(wm*16)*100 + wn*48 + f*16], acc[f],
                                100, wmma::mem_row_major);
    __syncthreads();

    /* elementwise GRU update: thread (jj = tid&31, ms = tid>>5) -> 8 rows */
    const int jj = tid & 31, ms = tid >> 5;
    const int jb = j0 + jj;
    const float bhr = b_hh[jb];
    const float bhz = b_hh[CH + jb];
    const float bhn = b_hh[2*CH + jb];
#pragma unroll
    for (int i = 0; i < 8; i++) {
        int mrow = ms * 8 + i;
        int m = m0 + mrow;
        float ghr = sgh[mrow*100 + jj]      + bhr;
        float ghz = sgh[mrow*100 + 32 + jj] + bhz;
        float ghn = sgh[mrow*100 + 64 + jj] + bhn;
        int b = m / CP, p = m - b * CP;
        size_t grow = (size_t)(b * CT + t) * CP + p;
        const float* gxr = gx + grow * (3*CH);
        float xr = gxr[jb], xz = gxr[CH + jb], xn = gxr[2*CH + jb];
        float hold = h_in[(size_t)m * CH + jb];
        float r = 1.f / (1.f + expf(-(xr + ghr)));
        float z = 1.f / (1.f + expf(-(xz + ghz)));
        float n = tanhf(xn + r * ghn);
        float hn = (1.f - z) * n + z * hold;
        size_t ho = (size_t)m * CH + jb;
        h_out[ho] = hn;
        __nv_bfloat16 hh = __float2bfloat16(hn);
        hh_out[ho] = hh;
        hl_out[ho] = __float2bfloat16(hn - __bfloat162float(hh));
        hid[grow * CH + jb] = hn;
    }
}

/* ---------------- heads (R7-proven) -------------------------------------- */
__global__ __launch_bounds__(256) void action_head(
    const float* __restrict__ hid, const float* __restrict__ W,
    const float* __restrict__ bias, float* __restrict__ out)
{
    __shared__ float Ws[9 * CH];
    for (int i = threadIdx.x; i < 9 * CH; i += 256) Ws[i] = W[i];
    __syncthreads();
    const int warp = threadIdx.x >> 5, lane = threadIdx.x & 31;
    const int m = blockIdx.x * 8 + warp;
    const float* hr = hid + (size_t)m * CH;
    float p[9];
#pragma unroll
    for (int a = 0; a < 9; a++) p[a] = 0.f;
    for (int kk = 0; kk < CH/32; kk++) {
        int k = lane + 32*kk;
        float v = hr[k];
#pragma unroll
        for (int a = 0; a < 9; a++) p[a] += v * Ws[a*CH + k];
    }
#pragma unroll
    for (int a = 0; a < 9; a++) {
        float s = p[a];
#pragma unroll
        for (int o = 16; o > 0; o >>= 1) s += __shfl_down_sync(0xffffffffu, s, o);
        if (lane == 0) out[(size_t)m * 9 + a] = s + bias[a];
    }
}

__global__ __launch_bounds__(256) void activity_head(
    const float* __restrict__ hid, const float* __restrict__ W,
    const float* __restrict__ bias, float* __restrict__ out)
{
    __shared__ float Ws[8 * CH];
    for (int i = threadIdx.x; i < 8 * CH; i += 256) Ws[i] = W[i];
    __syncthreads();
    const int warp = threadIdx.x >> 5, lane = threadIdx.x & 31;
    const int bt = blockIdx.x * 8 + warp;
    const float* base = hid + (size_t)bt * CP * CH;
    float p[8];
#pragma unroll
    for (int a = 0; a < 8; a++) p[a] = 0.f;
    for (int kk = 0; kk < CH/32; kk++) {
        int k = lane + 32*kk;
        float v = base[k];
#pragma unroll
        for (int pp = 1; pp < CP; pp++) v = fmaxf(v, base[(size_t)pp*CH + k]);
#pragma unroll
        for (int a = 0; a < 8; a++) p[a] += v * Ws[a*CH + k];
    }
#pragma unroll
    for (int a = 0; a < 8; a++) {
        float s = p[a];
#pragma unroll
        for (int o = 16; o > 0; o >>= 1) s += __shfl_down_sync(0xffffffffu, s, o);
        if (lane == 0) out[(size_t)bt * 8 + a] = s + bias[a];
    }
}

__global__ void zero_kernel(float* p, int n) {
    int i = blockIdx.x * 256 + threadIdx.x;
    if (i < n) p[i] = 0.f;
}

/* ---------------- launcher ----------------------------------------------- */
extern "C" void kernel_launch(void* const* d_in, const int* in_sizes, int n_in,
                              void* d_out, int out_size)
{
    const float* feature = (const float*)d_in[0];
    const float* W_embed = (const float*)d_in[1];
    const float* b_embed = (const float*)d_in[2];
    const float* W_ih    = (const float*)d_in[3];
    const float* W_hh    = (const float*)d_in[4];
    const float* b_ih    = (const float*)d_in[5];
    const float* b_hh    = (const float*)d_in[6];
    const float* W_act   = (const float*)d_in[7];
    const float* b_act   = (const float*)d_in[8];
    const float* W_activ = (const float*)d_in[9];
    const float* b_activ = (const float*)d_in[10];
    float* out = (float*)d_out;

    float *pgx, *pxf, *phid, *ph0, *ph1;
    __nv_bfloat16 *pfh, *pfl, *pxh, *pxl, *pWeh, *pWel, *pWih, *pWil;
    __nv_bfloat16 *pWhh, *pWhl, *phh0, *phl0, *phh1, *phl1;
    cudaGetSymbolAddress((void**)&pgx,  g_gx);
    cudaGetSymbolAddress((void**)&pxf,  g_xf);
    cudaGetSymbolAddress((void**)&phid, g_hid);
    cudaGetSymbolAddress((void**)&ph0,  g_h0);
    cudaGetSymbolAddress((void**)&ph1,  g_h1);
    cudaGetSymbolAddress((void**)&pfh,  g_fh);
    cudaGetSymbolAddress((void**)&pfl,  g_fl);
    cudaGetSymbolAddress((void**)&pxh,  g_xh);
    cudaGetSymbolAddress((void**)&pxl,  g_xl);
    cudaGetSymbolAddress((void**)&pWeh, g_Weh);
    cudaGetSymbolAddress((void**)&pWel, g_Wel);
    cudaGetSymbolAddress((void**)&pWih, g_Wih);
    cudaGetSymbolAddress((void**)&pWil, g_Wil);
    cudaGetSymbolAddress((void**)&pWhh, g_Whh);
    cudaGetSymbolAddress((void**)&pWhl, g_Whl);
    cudaGetSymbolAddress((void**)&phh0, g_hh0);
    cudaGetSymbolAddress((void**)&phl0, g_hl0);
    cudaGetSymbolAddress((void**)&phh1, g_hh1);
    cudaGetSymbolAddress((void**)&phl1, g_hl1);

    /* h0 = 0 (t=0 epilogue reads hold from it; GEMM skipped) */
    zero_kernel<<<(CBP*CH + 255)/256, 256>>>(ph0, CBP*CH);

    /* fp32 -> bf16 hi/lo conversions */
    cvt_hilo<<<(CM*CE + 255)/256, 256>>>(feature, pfh, pfl, CM*CE);
    cvt_hilo<<<(CH*CE + 255)/256, 256>>>(W_embed, pWeh, pWel, CH*CE);
    cvt_hilo<<<(3*CH*CH + 255)/256, 256>>>(W_ih, pWih, pWil, 3*CH*CH);
    cvt_hilo<<<(3*CH*CH + 255)/256, 256>>>(W_hh, pWhh, pWhl, 3*CH*CH);

    /* xraw = feature @ W_embed^T ; x = tanh(xraw + b) -> bf16 hi/lo */
    gemm_wmma<<<dim3(CH/128, CM/128), 256>>>(pfh, pfl, pWeh, pWel, pxf,
                                             CH, CE);
    tanh_hilo<<<dim3(CH/256, CM), 256>>>(pxf, b_embed, pxh, pxl);

    /* gx = x @ W_ih^T + b_ih  (fp32) */
    gemm_wmma<<<dim3(3*CH/128, CM/128), 256>>>(pxh, pxl, pWih, pWil, pgx,
                                               3*CH, CH);
    bias2d<<<dim3(3*CH/256, CM), 256>>>(pgx, b_ih, 3*CH);

    /* GRU scan, double-buffered state (fp32 + bf16 hi/lo) */
    float *hin = ph0, *hout = ph1;
    __nv_bfloat16 *hhin = phh0, *hlin = phl0, *hhout = phh1, *hlout = phl1;
    for (int t = 0; t < CT; ++t) {
        gru_step_tc<<<dim3(CH/32, CBP/64), 256>>>(
            hin, hhin, hlin, hout, hhout, hlout,
            pgx, pWhh, pWhl, b_hh, phid, t);
        float* tf = hin; hin = hout; hout = tf;
        __nv_bfloat16* t1 = hhin; hhin = hhout; hhout = t1;
        __nv_bfloat16* t2 = hlin; hlin = hlout; hlout = t2;
    }

    /* heads: action logits [15360,9] then activity logits [1280,8] */
    action_head<<<CM/8, 256>>>(phid, W_act, b_act, out);
    activity_head<<<(CB*CT)/8, 256>>>(phid, W_activ, b_activ,
                                      out + (size_t)CM * 9);
}